// round 7
// baseline (speedup 1.0000x reference)
#include <cuda_runtime.h>
#include <cuda_fp16.h>
#include <cstdint>

#define BB 32
#define LL 2048
#define DD 64

#define QT   32            // q rows per CTA
#define KTA  128           // k per tile (both phases)
#define NKT  (LL / KTA)    // 16

#define QSP  68            // q_s stride (floats)
#define KSP  68            // k_s stride (floats)
#define SCP  2056          // scores stride (halfs)  (2056/2 mod 32 = 4 -> conflict-free frags)
#define VTP  136           // vT stride (halfs)

// smem byte offsets
#define QS_OFF   0                         // float[32*68]    = 8704
#define KS_OFF   8704                      // float[128*68]   = 34816  (phase A)
#define VT_OFF   8704                      // half [64*136]   = 17408  (phase B, overlaps KS)
#define SC_OFF   43520                     // half [32*2056]  = 131584
#define PART_OFF 175104                    // float[32*8]     = 1024
#define RINV_OFF 176128                    // float[32]       = 128
#define SMEM_TOTAL 176384

__device__ float g_qn[(size_t)BB * LL * DD];   // tf32-rounded normalized q
__device__ float g_kn[(size_t)BB * LL * DD];   // tf32-rounded normalized k

// ---------------- helpers ----------------
__device__ __forceinline__ uint32_t f2tf32(float x) {
    uint32_t u;
    asm("cvt.rna.tf32.f32 %0, %1;" : "=r"(u) : "f"(x));
    return u;
}
__device__ __forceinline__ void mma_tf32(float* c, const uint32_t* a, const uint32_t* b) {
    asm volatile(
        "mma.sync.aligned.m16n8k8.row.col.f32.tf32.tf32.f32 "
        "{%0,%1,%2,%3}, {%4,%5,%6,%7}, {%8,%9}, {%0,%1,%2,%3};"
        : "+f"(c[0]), "+f"(c[1]), "+f"(c[2]), "+f"(c[3])
        : "r"(a[0]), "r"(a[1]), "r"(a[2]), "r"(a[3]), "r"(b[0]), "r"(b[1]));
}
__device__ __forceinline__ void mma_f16(float* c, const uint32_t* a, const uint32_t* b) {
    asm volatile(
        "mma.sync.aligned.m16n8k16.row.col.f32.f16.f16.f32 "
        "{%0,%1,%2,%3}, {%4,%5,%6,%7}, {%8,%9}, {%0,%1,%2,%3};"
        : "+f"(c[0]), "+f"(c[1]), "+f"(c[2]), "+f"(c[3])
        : "r"(a[0]), "r"(a[1]), "r"(a[2]), "r"(a[3]), "r"(b[0]), "r"(b[1]));
}

// ---------- Kernel 1: L2-normalize q,k rows; output rounded to tf32 ----------
__global__ __launch_bounds__(256) void norm_kernel(const float* __restrict__ q,
                                                   const float* __restrict__ k) {
    int t = threadIdx.x;
    int rowInBlk = t >> 4;
    int lane = t & 15;
    long long row = (long long)blockIdx.x * 16 + rowInBlk;

    const float* src;
    float* dst;
    long long r2 = row;
    if (r2 < (long long)BB * LL) {
        src = q; dst = g_qn;
    } else {
        src = k; dst = g_kn; r2 -= (long long)BB * LL;
    }
    const float4 v = *(const float4*)(src + r2 * DD + lane * 4);
    float ss = v.x * v.x + v.y * v.y + v.z * v.z + v.w * v.w;
#pragma unroll
    for (int o = 8; o; o >>= 1) ss += __shfl_xor_sync(0xffffffffu, ss, o, 16);
    float inv = 1.0f / fmaxf(sqrtf(ss), 1e-12f);
    float4 o4;
    o4.x = __uint_as_float(f2tf32(v.x * inv));
    o4.y = __uint_as_float(f2tf32(v.y * inv));
    o4.z = __uint_as_float(f2tf32(v.z * inv));
    o4.w = __uint_as_float(f2tf32(v.w * inv));
    *(float4*)(dst + r2 * DD + lane * 4) = o4;
}

// ---------- Kernel 2: fused attention. grid (LL/QT=64, BB), 256 threads ----------
// Phase A: QK tf32 HMMA -> masked s+1 -> fp16 scores in smem + rowsums.
// Phase B: attn = fp16(s) * rinv written once; PV fp16 HMMA on raw scores;
//          O rows scaled by rinv at the end.
__global__ __launch_bounds__(256, 1) void fused_kernel(const int* __restrict__ mask,
                                                       const float* __restrict__ v,
                                                       float* __restrict__ attn,
                                                       float* __restrict__ out) {
    extern __shared__ char smem[];
    float*  q_s  = (float*)(smem + QS_OFF);
    float*  k_s  = (float*)(smem + KS_OFF);
    __half* vT   = (__half*)(smem + VT_OFF);
    __half* sc   = (__half*)(smem + SC_OFF);
    float*  part = (float*)(smem + PART_OFF);
    float*  rinv = (float*)(smem + RINV_OFF);

    const int b  = blockIdx.y;
    const int q0 = blockIdx.x * QT;
    const int t  = threadIdx.x;
    const int w  = t >> 5, lane = t & 31;
    const int g  = lane >> 2, c = lane & 3;
    const int n0w = w * 16;                 // this warp's 16 k-cols within tile

    // stage q tile [32][64] (already tf32 bits)
    {
        int r = t >> 3, c8 = (t & 7) * 8;
        const float* qp = g_qn + ((size_t)b * LL + q0 + r) * DD + c8;
        *(float4*)&q_s[r * QSP + c8]     = *(const float4*)qp;
        *(float4*)&q_s[r * QSP + c8 + 4] = *(const float4*)(qp + 4);
    }

    const float* kn = g_kn + (size_t)b * LL * DD;
    const int* mbase = mask + ((size_t)b * LL + q0) * LL;

    float rs[4] = {0.f, 0.f, 0.f, 0.f};

    // ================= Phase A =================
    for (int kt = 0; kt < NKT; kt++) {
        __syncthreads();
        // stage k tile [128][64]
        {
            int kr = t >> 1, kh = (t & 1) * 32;
            const float* kp = kn + ((size_t)kt * KTA + kr) * DD + kh;
#pragma unroll
            for (int i = 0; i < 8; i++)
                *(float4*)&k_s[kr * KSP + kh + i * 4] = *(const float4*)(kp + i * 4);
        }
        __syncthreads();

        // prefetch mask for this warp's tile (hidden behind the GEMM)
        int2 mpre[2][2][2];   // [mf][rowhalf][nf]
#pragma unroll
        for (int mf = 0; mf < 2; mf++)
#pragma unroll
            for (int h = 0; h < 2; h++) {
                int row = mf * 16 + h * 8 + g;
                const int* mr = mbase + (size_t)row * LL + (size_t)kt * KTA + n0w;
#pragma unroll
                for (int nf = 0; nf < 2; nf++)
                    mpre[mf][h][nf] = __ldcs((const int2*)(mr + nf * 8 + 2 * c));
            }

        float acc[2][2][4];
#pragma unroll
        for (int mf = 0; mf < 2; mf++)
#pragma unroll
            for (int nf = 0; nf < 2; nf++)
#pragma unroll
                for (int e = 0; e < 4; e++) acc[mf][nf][e] = 0.f;

#pragma unroll
        for (int s = 0; s < 8; s++) {
            uint32_t a[2][4];
#pragma unroll
            for (int mf = 0; mf < 2; mf++) {
                int rbase = (mf * 16 + g) * QSP + s * 8 + c;
                a[mf][0] = __float_as_uint(q_s[rbase]);
                a[mf][1] = __float_as_uint(q_s[rbase + 8 * QSP]);
                a[mf][2] = __float_as_uint(q_s[rbase + 4]);
                a[mf][3] = __float_as_uint(q_s[rbase + 8 * QSP + 4]);
            }
#pragma unroll
            for (int nf = 0; nf < 2; nf++) {
                int nbase = (n0w + nf * 8 + g) * KSP + s * 8 + c;
                uint32_t bb[2];
                bb[0] = __float_as_uint(k_s[nbase]);
                bb[1] = __float_as_uint(k_s[nbase + 4]);
                mma_tf32(acc[0][nf], a[0], bb);
                mma_tf32(acc[1][nf], a[1], bb);
            }
        }

        // epilogue: mask, +1, fp16 scores, rowsums
#pragma unroll
        for (int mf = 0; mf < 2; mf++) {
            int row0 = mf * 16 + g;
#pragma unroll
            for (int nf = 0; nf < 2; nf++) {
                int col = kt * KTA + n0w + nf * 8 + 2 * c;
                int2 mA = mpre[mf][0][nf];
                int2 mB = mpre[mf][1][nf];
                float s0 = mA.x ? 0.f : acc[mf][nf][0] + 1.f;
                float s1 = mA.y ? 0.f : acc[mf][nf][1] + 1.f;
                float s2 = mB.x ? 0.f : acc[mf][nf][2] + 1.f;
                float s3 = mB.y ? 0.f : acc[mf][nf][3] + 1.f;
                rs[mf * 2 + 0] += s0 + s1;
                rs[mf * 2 + 1] += s2 + s3;
                *(__half2*)&sc[row0 * SCP + col]       = __floats2half2_rn(s0, s1);
                *(__half2*)&sc[(row0 + 8) * SCP + col] = __floats2half2_rn(s2, s3);
            }
        }
    }

    // rowsum reduce: lanes c=0..3 share rows
#pragma unroll
    for (int i = 0; i < 4; i++) {
        float vs = rs[i];
        vs += __shfl_xor_sync(0xffffffffu, vs, 1);
        vs += __shfl_xor_sync(0xffffffffu, vs, 2);
        rs[i] = vs;
    }
    if (c == 0) {
        part[(g) * 8 + w]      = rs[0];
        part[(g + 8) * 8 + w]  = rs[1];
        part[(g + 16) * 8 + w] = rs[2];
        part[(g + 24) * 8 + w] = rs[3];
    }
    __syncthreads();
    if (t < 32) {
        float s = 0.f;
#pragma unroll
        for (int j = 0; j < 8; j++) s += part[t * 8 + j];
        rinv[t] = 1.0f / fmaxf(s, 1e-12f);
    }
    __syncthreads();

    // ================= Phase B =================
    float oacc[2][4];
#pragma unroll
    for (int mf = 0; mf < 2; mf++)
#pragma unroll
        for (int e = 0; e < 4; e++) oacc[mf][e] = 0.f;

    const float* vb = v + (size_t)b * LL * DD;
    float* ab = attn + ((size_t)b * LL + q0) * LL;
    const int arow = t >> 3, aseg = (t & 7) * 16;   // attn-write mapping
    const int d0 = w * 8;                            // this warp's 8 d-cols

    for (int kt = 0; kt < NKT; kt++) {
        __syncthreads();
        // stage vT fp16 [64 d][128 k]
        {
            int kr = t >> 1, dh = (t & 1) * 32;
            const float* vp = vb + ((size_t)kt * KTA + kr) * DD + dh;
#pragma unroll
            for (int i = 0; i < 8; i++) {
                float4 x = *(const float4*)(vp + i * 4);
                int d = dh + i * 4;
                vT[(d + 0) * VTP + kr] = __float2half_rn(x.x);
                vT[(d + 1) * VTP + kr] = __float2half_rn(x.y);
                vT[(d + 2) * VTP + kr] = __float2half_rn(x.z);
                vT[(d + 3) * VTP + kr] = __float2half_rn(x.w);
            }
        }
        __syncthreads();

        // write final attn for this kt (normalized)
        {
            float ri = rinv[arow];
            float* ap = ab + (size_t)arow * LL + (size_t)kt * KTA + aseg;
            const __half2* sp = (const __half2*)&sc[arow * SCP + kt * KTA + aseg];
#pragma unroll
            for (int j = 0; j < 4; j++) {
                float2 f0 = __half22float2(sp[2 * j]);
                float2 f1 = __half22float2(sp[2 * j + 1]);
                float4 o;
                o.x = f0.x * ri; o.y = f0.y * ri;
                o.z = f1.x * ri; o.w = f1.y * ri;
                __stcs((float4*)(ap + 4 * j), o);
            }
        }

        // PV GEMM: fp16 m16n8k16, A = raw fp16 scores, B = vT
#pragma unroll
        for (int s = 0; s < 8; s++) {
            uint32_t a[2][4];
#pragma unroll
            for (int mf = 0; mf < 2; mf++) {
                int base = (mf * 16 + g) * SCP + kt * KTA + s * 16 + 2 * c;
                a[mf][0] = *(const uint32_t*)&sc[base];
                a[mf][1] = *(const uint32_t*)&sc[base + 8 * SCP];
                a[mf][2] = *(const uint32_t*)&sc[base + 8];
                a[mf][3] = *(const uint32_t*)&sc[base + 8 * SCP + 8];
            }
            int vbase = (d0 + g) * VTP + s * 16 + 2 * c;
            uint32_t bb[2];
            bb[0] = *(const uint32_t*)&vT[vbase];
            bb[1] = *(const uint32_t*)&vT[vbase + 8];
            mma_f16(oacc[0], a[0], bb);
            mma_f16(oacc[1], a[1], bb);
        }
    }

    // O epilogue: scale rows by rinv, write
#pragma unroll
    for (int mf = 0; mf < 2; mf++) {
        int row0 = mf * 16 + g;
        float r0 = rinv[row0], r1 = rinv[row0 + 8];
        float* o0 = out + ((size_t)b * LL + q0 + row0) * DD + d0 + 2 * c;
        float* o1 = o0 + (size_t)8 * DD;
        *(float2*)o0 = make_float2(oacc[mf][0] * r0, oacc[mf][1] * r0);
        *(float2*)o1 = make_float2(oacc[mf][2] * r1, oacc[mf][3] * r1);
    }
}

// ---------------- launch ----------------
extern "C" void kernel_launch(void* const* d_in, const int* in_sizes, int n_in,
                              void* d_out, int out_size) {
    const float* q = (const float*)d_in[0];
    const float* k = (const float*)d_in[1];
    const float* v = (const float*)d_in[2];
    const int* mask = (const int*)d_in[3];

    float* out = (float*)d_out;
    float* attn = out + (size_t)BB * LL * DD;

    cudaFuncSetAttribute(fused_kernel, cudaFuncAttributeMaxDynamicSharedMemorySize,
                         SMEM_TOTAL);

    norm_kernel<<<(2 * BB * LL) / 16, 256>>>(q, k);
    fused_kernel<<<dim3(LL / QT, BB), 256, SMEM_TOTAL>>>(mask, v, attn, out);
}

// round 8
// speedup vs baseline: 2.0352x; 2.0352x over previous
#include <cuda_runtime.h>
#include <cuda_fp16.h>
#include <cstdint>

#define BB 32
#define LL 2048
#define DD 64
#define NKT 16            // 2048 / 128

// qk smem (halfs strides)
#define QKSP 72
#define SCSP 136
#define QK_QS    0
#define QK_KS    18432
#define QK_SCS   36864
#define QK_PART  71680
#define QK_SMEM  72704

// pv smem
#define PV_SS    0
#define PV_VS    34816
#define PV_RINV  53248
#define PV_SMEM  53760

__device__ __half g_qh[(size_t)BB * LL * DD];
__device__ __half g_kh[(size_t)BB * LL * DD];
__device__ __half g_sc[(size_t)BB * LL * LL];   // raw masked s+1, fp16
__device__ float  g_rinv[(size_t)BB * LL];

// ---------------- helpers ----------------
__device__ __forceinline__ uint32_t smem_u32(const void* p) {
    uint32_t a;
    asm("{ .reg .u64 t; cvta.to.shared.u64 t, %1; cvt.u32.u64 %0, t; }" : "=r"(a) : "l"(p));
    return a;
}
__device__ __forceinline__ void ldsm_x4(uint32_t addr, uint32_t* r) {
    asm volatile("ldmatrix.sync.aligned.m8n8.x4.shared.b16 {%0,%1,%2,%3}, [%4];"
                 : "=r"(r[0]), "=r"(r[1]), "=r"(r[2]), "=r"(r[3]) : "r"(addr));
}
__device__ __forceinline__ void ldsm_x4t(uint32_t addr, uint32_t* r) {
    asm volatile("ldmatrix.sync.aligned.m8n8.x4.trans.shared.b16 {%0,%1,%2,%3}, [%4];"
                 : "=r"(r[0]), "=r"(r[1]), "=r"(r[2]), "=r"(r[3]) : "r"(addr));
}
__device__ __forceinline__ void mma_f16(float* c, const uint32_t* a, const uint32_t* b) {
    asm volatile(
        "mma.sync.aligned.m16n8k16.row.col.f32.f16.f16.f32 "
        "{%0,%1,%2,%3}, {%4,%5,%6,%7}, {%8,%9}, {%0,%1,%2,%3};"
        : "+f"(c[0]), "+f"(c[1]), "+f"(c[2]), "+f"(c[3])
        : "r"(a[0]), "r"(a[1]), "r"(a[2]), "r"(a[3]), "r"(b[0]), "r"(b[1]));
}

// ---------- Kernel 1: normalize q,k -> fp16 ----------
__global__ __launch_bounds__(256) void norm_kernel(const float* __restrict__ q,
                                                   const float* __restrict__ k) {
    int t = threadIdx.x;
    int rowInBlk = t >> 4;
    int lane = t & 15;
    long long row = (long long)blockIdx.x * 16 + rowInBlk;

    const float* src;
    __half* dst;
    long long r2 = row;
    if (r2 < (long long)BB * LL) { src = q; dst = g_qh; }
    else { src = k; dst = g_kh; r2 -= (long long)BB * LL; }

    const float4 v = *(const float4*)(src + r2 * DD + lane * 4);
    float ss = v.x * v.x + v.y * v.y + v.z * v.z + v.w * v.w;
#pragma unroll
    for (int o = 8; o; o >>= 1) ss += __shfl_xor_sync(0xffffffffu, ss, o, 16);
    float inv = 1.0f / fmaxf(sqrtf(ss), 1e-12f);
    __half2 h01 = __floats2half2_rn(v.x * inv, v.y * inv);
    __half2 h23 = __floats2half2_rn(v.z * inv, v.w * inv);
    uint2 u;
    u.x = *(uint32_t*)&h01;
    u.y = *(uint32_t*)&h23;
    *(uint2*)(dst + r2 * DD + lane * 4) = u;
}

// ---------- Kernel 2: QK (fp16 HMMA + ldmatrix) -> fp16 scratch + rowsums ----------
// grid (16, 32), 256 thr. warp w: mi=w&3 (32q), ni=w>>2 (64k). tile 128q x 128k.
__global__ __launch_bounds__(256, 2) void qk_kernel(const int* __restrict__ mask) {
    extern __shared__ char smem[];
    __half* q_s  = (__half*)(smem + QK_QS);
    __half* k_s  = (__half*)(smem + QK_KS);
    __half* sc_s = (__half*)(smem + QK_SCS);
    float*  part = (float*)(smem + QK_PART);
    const uint32_t smb = smem_u32(smem);

    const int b = blockIdx.y;
    const int q0 = blockIdx.x * 128;
    const int t = threadIdx.x;
    const int w = t >> 5, lane = t & 31;
    const int g = lane >> 2, c = lane & 3;
    const int m0 = (w & 3) * 32, ni = w >> 2, n0 = ni * 64;

    // stage q tile [128][64] fp16 (direct copy)
    {
        int r = t >> 1, sg = (t & 1) * 32;
        const __half* qp = g_qh + ((size_t)b * LL + q0 + r) * DD + sg;
#pragma unroll
        for (int i = 0; i < 4; i++)
            *(uint4*)&q_s[r * QKSP + sg + i * 8] = *(const uint4*)(qp + i * 8);
    }

    const uint32_t aptr = smb + QK_QS + (uint32_t)(m0 + (lane & 15)) * 144 + (lane >> 4) * 16;
    const uint32_t bptr = smb + QK_KS +
        (uint32_t)(n0 + ((lane >> 4) << 3) + (lane & 7)) * 144 + ((lane >> 3) & 1) * 16;

    const __half* kn = g_kh + (size_t)b * LL * DD;
    float rs[4] = {0.f, 0.f, 0.f, 0.f};

    for (int kt = 0; kt < NKT; kt++) {
        __syncthreads();
        {   // stage k tile [128][64]
            int r = t >> 1, sg = (t & 1) * 32;
            const __half* kp = kn + ((size_t)kt * 128 + r) * DD + sg;
#pragma unroll
            for (int i = 0; i < 4; i++)
                *(uint4*)&k_s[r * QKSP + sg + i * 8] = *(const uint4*)(kp + i * 8);
        }
        __syncthreads();

        float acc[2][8][4];
#pragma unroll
        for (int mf = 0; mf < 2; mf++)
#pragma unroll
            for (int nf = 0; nf < 8; nf++)
#pragma unroll
                for (int e = 0; e < 4; e++) acc[mf][nf][e] = 0.f;

#pragma unroll
        for (int s = 0; s < 4; s++) {
            uint32_t a0[4], a1[4];
            ldsm_x4(aptr + s * 32, a0);
            ldsm_x4(aptr + 16 * 144 + s * 32, a1);
#pragma unroll
            for (int nfp = 0; nfp < 4; nfp++) {
                uint32_t bb[4];
                ldsm_x4(bptr + (uint32_t)nfp * 16 * 144 + s * 32, bb);
                mma_f16(acc[0][nfp * 2],     a0, bb);
                mma_f16(acc[0][nfp * 2 + 1], a0, bb + 2);
                mma_f16(acc[1][nfp * 2],     a1, bb);
                mma_f16(acc[1][nfp * 2 + 1], a1, bb + 2);
            }
        }

        // epilogue: mask, +1, rowsums, fp16 fragments -> sc_s
        const int* mbase = mask + ((size_t)b * LL + q0) * LL + (size_t)kt * 128;
#pragma unroll
        for (int mf = 0; mf < 2; mf++) {
            int r0 = m0 + mf * 16 + g;
#pragma unroll
            for (int nf = 0; nf < 8; nf++) {
                int col = n0 + nf * 8 + 2 * c;
                int2 mA = __ldcs((const int2*)(mbase + (size_t)r0 * LL + col));
                int2 mB = __ldcs((const int2*)(mbase + (size_t)(r0 + 8) * LL + col));
                float s0 = mA.x ? 0.f : acc[mf][nf][0] + 1.f;
                float s1 = mA.y ? 0.f : acc[mf][nf][1] + 1.f;
                float s2 = mB.x ? 0.f : acc[mf][nf][2] + 1.f;
                float s3 = mB.y ? 0.f : acc[mf][nf][3] + 1.f;
                rs[mf * 2 + 0] += s0 + s1;
                rs[mf * 2 + 1] += s2 + s3;
                *(__half2*)&sc_s[r0 * SCSP + col]       = __floats2half2_rn(s0, s1);
                *(__half2*)&sc_s[(r0 + 8) * SCSP + col] = __floats2half2_rn(s2, s3);
            }
        }
        __syncthreads();
        // coalesced write: warp owns rows w*16..w*16+15, lane covers 4 halfs
#pragma unroll
        for (int i = 0; i < 16; i++) {
            int row = w * 16 + i;
            uint2 val = *(const uint2*)&sc_s[row * SCSP + lane * 4];
            __stcs((uint2*)(g_sc + ((size_t)b * LL + q0 + row) * LL +
                            (size_t)kt * 128 + lane * 4), val);
        }
    }

    // rowsums: reduce over c lanes, combine two ni halves via smem
#pragma unroll
    for (int i = 0; i < 4; i++) {
        float vs = rs[i];
        vs += __shfl_xor_sync(0xffffffffu, vs, 1);
        vs += __shfl_xor_sync(0xffffffffu, vs, 2);
        rs[i] = vs;
    }
    if (c == 0) {
        part[(m0 + g) * 2 + ni]      = rs[0];
        part[(m0 + g + 8) * 2 + ni]  = rs[1];
        part[(m0 + 16 + g) * 2 + ni] = rs[2];
        part[(m0 + 24 + g) * 2 + ni] = rs[3];
    }
    __syncthreads();
    if (t < 128)
        g_rinv[(size_t)b * LL + q0 + t] =
            1.0f / fmaxf(part[t * 2] + part[t * 2 + 1], 1e-12f);
}

// ---------- Kernel 3: PV (fp16 HMMA + ldmatrix) + final attn write ----------
// grid (16, 32), 256 thr. warp w: mi=w&3 (32q), ni=w>>2 (32d).
__global__ __launch_bounds__(256, 3) void pv_kernel(const float* __restrict__ v,
                                                    float* __restrict__ attn,
                                                    float* __restrict__ out) {
    extern __shared__ char smem[];
    __half* s_s  = (__half*)(smem + PV_SS);
    __half* v_s  = (__half*)(smem + PV_VS);
    float*  rinv = (float*)(smem + PV_RINV);
    const uint32_t smb = smem_u32(smem);

    const int b = blockIdx.y;
    const int q0 = blockIdx.x * 128;
    const int t = threadIdx.x;
    const int w = t >> 5, lane = t & 31;
    const int g = lane >> 2, c = lane & 3;
    const int m0 = (w & 3) * 32, n0 = (w >> 2) * 32;

    if (t < 128) rinv[t] = g_rinv[(size_t)b * LL + q0 + t];

    const uint32_t aptr = smb + PV_SS + (uint32_t)(m0 + (lane & 15)) * 272 + (lane >> 4) * 16;
    const uint32_t vptr = smb + PV_VS + (uint32_t)(lane & 15) * 144 + (lane >> 4) * 16;

    float oacc[2][4][4];
#pragma unroll
    for (int mf = 0; mf < 2; mf++)
#pragma unroll
        for (int nf = 0; nf < 4; nf++)
#pragma unroll
            for (int e = 0; e < 4; e++) oacc[mf][nf][e] = 0.f;

    const float* vb = v + (size_t)b * LL * DD;
    __syncthreads();   // rinv visible

    for (int kt = 0; kt < NKT; kt++) {
        __syncthreads();   // previous GEMM done with smem
        // stage s_s (raw fp16) + write final attn (normalized fp32)
#pragma unroll
        for (int i = 0; i < 16; i++) {
            int row = w * 16 + i;
            const __half* sp = g_sc + ((size_t)b * LL + q0 + row) * LL +
                               (size_t)kt * 128 + lane * 4;
            uint2 raw = __ldcs((const uint2*)sp);
            *(uint2*)&s_s[row * SCSP + lane * 4] = raw;
            float ri = rinv[row];
            __half2 h0 = *(__half2*)&raw.x;
            __half2 h1 = *(__half2*)&raw.y;
            float2 f0 = __half22float2(h0);
            float2 f1 = __half22float2(h1);
            float4 o = make_float4(f0.x * ri, f0.y * ri, f1.x * ri, f1.y * ri);
            __stcs((float4*)(attn + ((size_t)b * LL + q0 + row) * LL +
                             (size_t)kt * 128 + lane * 4), o);
        }
        // stage v tile [128 k][64 d] fp16, natural layout
#pragma unroll
        for (int i = 0; i < 16; i++) {
            int kr = w * 16 + i;
            float2 vv = *(const float2*)(vb + ((size_t)kt * 128 + kr) * DD + lane * 2);
            *(__half2*)&v_s[kr * QKSP + lane * 2] = __floats2half2_rn(vv.x, vv.y);
        }
        __syncthreads();

#pragma unroll
        for (int s = 0; s < 8; s++) {
            uint32_t a0[4], a1[4];
            ldsm_x4(aptr + s * 32, a0);
            ldsm_x4(aptr + 16 * 272 + s * 32, a1);
#pragma unroll
            for (int nfp = 0; nfp < 2; nfp++) {
                uint32_t bb[4];
                ldsm_x4t(vptr + (uint32_t)s * 2304 + (uint32_t)(n0 + nfp * 16) * 2, bb);
                mma_f16(oacc[0][nfp * 2],     a0, bb);
                mma_f16(oacc[0][nfp * 2 + 1], a0, bb + 2);
                mma_f16(oacc[1][nfp * 2],     a1, bb);
                mma_f16(oacc[1][nfp * 2 + 1], a1, bb + 2);
            }
        }
    }

    // O epilogue: scale rows by rinv, write
#pragma unroll
    for (int mf = 0; mf < 2; mf++) {
        int row = m0 + mf * 16 + g;
        float r0 = rinv[row], r1 = rinv[row + 8];
        float* o0 = out + ((size_t)b * LL + q0 + row) * DD;
        float* o1 = o0 + (size_t)8 * DD;
#pragma unroll
        for (int nf = 0; nf < 4; nf++) {
            int col = n0 + nf * 8 + 2 * c;
            *(float2*)(o0 + col) = make_float2(oacc[mf][nf][0] * r0, oacc[mf][nf][1] * r0);
            *(float2*)(o1 + col) = make_float2(oacc[mf][nf][2] * r1, oacc[mf][nf][3] * r1);
        }
    }
}

// ---------------- launch ----------------
extern "C" void kernel_launch(void* const* d_in, const int* in_sizes, int n_in,
                              void* d_out, int out_size) {
    const float* q = (const float*)d_in[0];
    const float* k = (const float*)d_in[1];
    const float* v = (const float*)d_in[2];
    const int* mask = (const int*)d_in[3];

    float* out = (float*)d_out;
    float* attn = out + (size_t)BB * LL * DD;

    cudaFuncSetAttribute(qk_kernel, cudaFuncAttributeMaxDynamicSharedMemorySize, QK_SMEM);
    cudaFuncSetAttribute(pv_kernel, cudaFuncAttributeMaxDynamicSharedMemorySize, PV_SMEM);

    norm_kernel<<<(2 * BB * LL) / 16, 256>>>(q, k);
    qk_kernel<<<dim3(LL / 128, BB), 256, QK_SMEM>>>(mask);
    pv_kernel<<<dim3(LL / 128, BB), 256, PV_SMEM>>>(v, attn, out);
}

// round 9
// speedup vs baseline: 3.1811x; 1.5630x over previous
#include <cuda_runtime.h>
#include <cuda_fp16.h>
#include <cstdint>

#define BB 32
#define LL 2048
#define DD 64
#define NKT 16            // 2048 / 128

// strides in halfs
#define KSP 72            // q_s / k_s / v_s row stride
#define SSP 136           // s_s row stride

// pass1 smem (bytes)
#define P1_QS   0
#define P1_KS   18432
#define P1_BMT  36864     // uint32[512]
#define P1_PART 38912     // float[256]
#define P1_SMEM 39936

// pass2 smem (bytes)
#define P2_QS   0
#define P2_KS   18432
#define P2_VS   36864
#define P2_SS   55296
#define P2_BMT  90112     // uint32[512]
#define P2_RINV 92160     // float[128]
#define P2_SMEM 92672

__device__ __half   g_qh[(size_t)BB * LL * DD];
__device__ __half   g_kh[(size_t)BB * LL * DD];
__device__ uint32_t g_bm[(size_t)BB * LL * (LL / 32)];   // 16.8 MB bitmask
__device__ float    g_rinv[(size_t)BB * LL];

// ---------------- helpers ----------------
__device__ __forceinline__ uint32_t smem_u32(const void* p) {
    uint32_t a;
    asm("{ .reg .u64 t; cvta.to.shared.u64 t, %1; cvt.u32.u64 %0, t; }" : "=r"(a) : "l"(p));
    return a;
}
__device__ __forceinline__ void ldsm_x4(uint32_t addr, uint32_t* r) {
    asm volatile("ldmatrix.sync.aligned.m8n8.x4.shared.b16 {%0,%1,%2,%3}, [%4];"
                 : "=r"(r[0]), "=r"(r[1]), "=r"(r[2]), "=r"(r[3]) : "r"(addr));
}
__device__ __forceinline__ void ldsm_x4t(uint32_t addr, uint32_t* r) {
    asm volatile("ldmatrix.sync.aligned.m8n8.x4.trans.shared.b16 {%0,%1,%2,%3}, [%4];"
                 : "=r"(r[0]), "=r"(r[1]), "=r"(r[2]), "=r"(r[3]) : "r"(addr));
}
__device__ __forceinline__ void mma_f16(float* c, const uint32_t* a, const uint32_t* b) {
    asm volatile(
        "mma.sync.aligned.m16n8k16.row.col.f32.f16.f16.f32 "
        "{%0,%1,%2,%3}, {%4,%5,%6,%7}, {%8,%9}, {%0,%1,%2,%3};"
        : "+f"(c[0]), "+f"(c[1]), "+f"(c[2]), "+f"(c[3])
        : "r"(a[0]), "r"(a[1]), "r"(a[2]), "r"(a[3]), "r"(b[0]), "r"(b[1]));
}

// ---------- Kernel 1: normalize q,k -> fp16 ----------
__global__ __launch_bounds__(256) void norm_kernel(const float* __restrict__ q,
                                                   const float* __restrict__ k) {
    int t = threadIdx.x;
    int rowInBlk = t >> 4;
    int lane = t & 15;
    long long row = (long long)blockIdx.x * 16 + rowInBlk;

    const float* src;
    __half* dst;
    long long r2 = row;
    if (r2 < (long long)BB * LL) { src = q; dst = g_qh; }
    else { src = k; dst = g_kh; r2 -= (long long)BB * LL; }

    const float4 v = *(const float4*)(src + r2 * DD + lane * 4);
    float ss = v.x * v.x + v.y * v.y + v.z * v.z + v.w * v.w;
#pragma unroll
    for (int o = 8; o; o >>= 1) ss += __shfl_xor_sync(0xffffffffu, ss, o, 16);
    float inv = 1.0f / fmaxf(sqrtf(ss), 1e-12f);
    __half2 h01 = __floats2half2_rn(v.x * inv, v.y * inv);
    __half2 h23 = __floats2half2_rn(v.z * inv, v.w * inv);
    uint2 u;
    u.x = *(uint32_t*)&h01;
    u.y = *(uint32_t*)&h23;
    *(uint2*)(dst + r2 * DD + lane * 4) = u;
}

// ---------- Pass 1: QK rowsums + mask bitpack ----------
// grid (16, 32), 256 thr. warp w: m0=(w&3)*32 (32q), n0=(w>>2)*64 (64k).
__global__ __launch_bounds__(256, 2) void pass1_kernel(const int* __restrict__ mask) {
    extern __shared__ char smem[];
    __half*   q_s  = (__half*)(smem + P1_QS);
    __half*   k_s  = (__half*)(smem + P1_KS);
    uint32_t* bmt  = (uint32_t*)(smem + P1_BMT);
    float*    part = (float*)(smem + P1_PART);
    const uint32_t smb = smem_u32(smem);

    const int b = blockIdx.y;
    const int q0 = blockIdx.x * 128;
    const int t = threadIdx.x;
    const int w = t >> 5, lane = t & 31;
    const int g = lane >> 2, c = lane & 3;
    const int m0 = (w & 3) * 32, ni = w >> 2, n0 = ni * 64;

    // stage q tile [128][64] fp16
    {
        int r = t >> 1, sg = (t & 1) * 32;
        const __half* qp = g_qh + ((size_t)b * LL + q0 + r) * DD + sg;
#pragma unroll
        for (int i = 0; i < 4; i++)
            *(uint4*)&q_s[r * KSP + sg + i * 8] = *(const uint4*)(qp + i * 8);
    }

    const uint32_t aptr = smb + P1_QS + (uint32_t)(m0 + (lane & 15)) * 144 + (lane >> 4) * 16;
    const uint32_t bptr = smb + P1_KS +
        (uint32_t)(n0 + ((lane >> 4) << 3) + (lane & 7)) * 144 + ((lane >> 3) & 1) * 16;

    const __half* kn = g_kh + (size_t)b * LL * DD;
    float rs[4] = {0.f, 0.f, 0.f, 0.f};

    for (int kt = 0; kt < NKT; kt++) {
        __syncthreads();
        {   // stage k tile [128][64]
            int r = t >> 1, sg = (t & 1) * 32;
            const __half* kp = kn + ((size_t)kt * 128 + r) * DD + sg;
#pragma unroll
            for (int i = 0; i < 4; i++)
                *(uint4*)&k_s[r * KSP + sg + i * 8] = *(const uint4*)(kp + i * 8);
        }
        // ballot bitpack: warp w handles rows w*16..w*16+15
        {
            const int* mbase = mask + ((size_t)b * LL + q0) * LL + (size_t)kt * 128;
#pragma unroll
            for (int i = 0; i < 16; i++) {
                int row = w * 16 + i;
                const int* mr = mbase + (size_t)row * LL;
#pragma unroll
                for (int wq = 0; wq < 4; wq++) {
                    int mv = __ldcs(mr + wq * 32 + lane);
                    uint32_t bits = __ballot_sync(0xffffffffu, mv != 0);
                    if (lane == wq) bmt[row * 4 + wq] = bits;
                }
            }
        }
        __syncthreads();
        // persist bitmask tile (L2-resident for pass 2)
        if (t < 128)
            *(uint4*)&g_bm[((size_t)b * LL + q0 + t) * 64 + kt * 4] = *(const uint4*)&bmt[t * 4];

        // QK MMA
        float acc[2][8][4];
#pragma unroll
        for (int mf = 0; mf < 2; mf++)
#pragma unroll
            for (int nf = 0; nf < 8; nf++)
#pragma unroll
                for (int e = 0; e < 4; e++) acc[mf][nf][e] = 0.f;

#pragma unroll
        for (int s = 0; s < 4; s++) {
            uint32_t a0[4], a1[4];
            ldsm_x4(aptr + s * 32, a0);
            ldsm_x4(aptr + 16 * 144 + s * 32, a1);
#pragma unroll
            for (int nfp = 0; nfp < 4; nfp++) {
                uint32_t bb[4];
                ldsm_x4(bptr + (uint32_t)nfp * 16 * 144 + s * 32, bb);
                mma_f16(acc[0][nfp * 2],     a0, bb);
                mma_f16(acc[0][nfp * 2 + 1], a0, bb + 2);
                mma_f16(acc[1][nfp * 2],     a1, bb);
                mma_f16(acc[1][nfp * 2 + 1], a1, bb + 2);
            }
        }

        // rowsum epilogue (bits from smem)
#pragma unroll
        for (int mf = 0; mf < 2; mf++) {
            int r0 = m0 + mf * 16 + g;
#pragma unroll
            for (int nf = 0; nf < 8; nf++) {
                int col = n0 + nf * 8 + 2 * c;
                uint32_t wA = bmt[r0 * 4 + (col >> 5)];
                uint32_t wB = bmt[(r0 + 8) * 4 + (col >> 5)];
                int sh = col & 31;
                float s0 = ((wA >> sh) & 1u)       ? 0.f : acc[mf][nf][0] + 1.f;
                float s1 = ((wA >> (sh + 1)) & 1u) ? 0.f : acc[mf][nf][1] + 1.f;
                float s2 = ((wB >> sh) & 1u)       ? 0.f : acc[mf][nf][2] + 1.f;
                float s3 = ((wB >> (sh + 1)) & 1u) ? 0.f : acc[mf][nf][3] + 1.f;
                rs[mf * 2 + 0] += s0 + s1;
                rs[mf * 2 + 1] += s2 + s3;
            }
        }
    }

    // rowsums: reduce over c lanes, combine two ni halves via smem
#pragma unroll
    for (int i = 0; i < 4; i++) {
        float vs = rs[i];
        vs += __shfl_xor_sync(0xffffffffu, vs, 1);
        vs += __shfl_xor_sync(0xffffffffu, vs, 2);
        rs[i] = vs;
    }
    if (c == 0) {
        part[(m0 + g) * 2 + ni]      = rs[0];
        part[(m0 + g + 8) * 2 + ni]  = rs[1];
        part[(m0 + 16 + g) * 2 + ni] = rs[2];
        part[(m0 + 24 + g) * 2 + ni] = rs[3];
    }
    __syncthreads();
    if (t < 128)
        g_rinv[(size_t)b * LL + q0 + t] =
            1.0f / fmaxf(part[t * 2] + part[t * 2 + 1], 1e-12f);
}

// ---------- Pass 2: QK recompute -> attn write + PV ----------
// grid (16, 32), 256 thr. QK: m0=(w&3)*32, n0q=(w>>2)*64. PV: n0p=(w>>2)*32.
__global__ __launch_bounds__(256, 2) void pass2_kernel(const float* __restrict__ v,
                                                       float* __restrict__ attn,
                                                       float* __restrict__ out) {
    extern __shared__ char smem[];
    __half*   q_s  = (__half*)(smem + P2_QS);
    __half*   k_s  = (__half*)(smem + P2_KS);
    __half*   v_s  = (__half*)(smem + P2_VS);
    __half*   s_s  = (__half*)(smem + P2_SS);
    uint32_t* bmt  = (uint32_t*)(smem + P2_BMT);
    float*    rinv = (float*)(smem + P2_RINV);
    const uint32_t smb = smem_u32(smem);

    const int b = blockIdx.y;
    const int q0 = blockIdx.x * 128;
    const int t = threadIdx.x;
    const int w = t >> 5, lane = t & 31;
    const int g = lane >> 2, c = lane & 3;
    const int m0 = (w & 3) * 32;
    const int n0q = (w >> 2) * 64;
    const int n0p = (w >> 2) * 32;

    if (t < 128) rinv[t] = g_rinv[(size_t)b * LL + q0 + t];

    // stage q tile
    {
        int r = t >> 1, sg = (t & 1) * 32;
        const __half* qp = g_qh + ((size_t)b * LL + q0 + r) * DD + sg;
#pragma unroll
        for (int i = 0; i < 4; i++)
            *(uint4*)&q_s[r * KSP + sg + i * 8] = *(const uint4*)(qp + i * 8);
    }

    const uint32_t aptrq = smb + P2_QS + (uint32_t)(m0 + (lane & 15)) * 144 + (lane >> 4) * 16;
    const uint32_t bptrq = smb + P2_KS +
        (uint32_t)(n0q + ((lane >> 4) << 3) + (lane & 7)) * 144 + ((lane >> 3) & 1) * 16;
    const uint32_t aptrp = smb + P2_SS + (uint32_t)(m0 + (lane & 15)) * 272 + (lane >> 4) * 16;
    const uint32_t vptr  = smb + P2_VS + (uint32_t)(lane & 15) * 144 + (lane >> 4) * 16;

    float oacc[2][4][4];
#pragma unroll
    for (int mf = 0; mf < 2; mf++)
#pragma unroll
        for (int nf = 0; nf < 4; nf++)
#pragma unroll
            for (int e = 0; e < 4; e++) oacc[mf][nf][e] = 0.f;

    const __half* kn = g_kh + (size_t)b * LL * DD;
    const float*  vb = v + (size_t)b * LL * DD;

    for (int kt = 0; kt < NKT; kt++) {
        __syncthreads();   // prev PV / attn-write done with smem
        {   // stage k tile [128][64]
            int r = t >> 1, sg = (t & 1) * 32;
            const __half* kp = kn + ((size_t)kt * 128 + r) * DD + sg;
#pragma unroll
            for (int i = 0; i < 4; i++)
                *(uint4*)&k_s[r * KSP + sg + i * 8] = *(const uint4*)(kp + i * 8);
        }
        // stage v tile [128 k][64 d] fp16
#pragma unroll
        for (int i = 0; i < 16; i++) {
            int kr = w * 16 + i;
            float2 vv = *(const float2*)(vb + ((size_t)kt * 128 + kr) * DD + lane * 2);
            *(__half2*)&v_s[kr * KSP + lane * 2] = __floats2half2_rn(vv.x, vv.y);
        }
        // stage bitmask tile
        if (t < 128)
            *(uint4*)&bmt[t * 4] = *(const uint4*)&g_bm[((size_t)b * LL + q0 + t) * 64 + kt * 4];
        __syncthreads();

        // QK recompute, two 32-col halves (keeps register pressure down)
#pragma unroll
        for (int h = 0; h < 2; h++) {
            float acc[2][4][4];
#pragma unroll
            for (int mf = 0; mf < 2; mf++)
#pragma unroll
                for (int j = 0; j < 4; j++)
#pragma unroll
                    for (int e = 0; e < 4; e++) acc[mf][j][e] = 0.f;

#pragma unroll
            for (int s = 0; s < 4; s++) {
                uint32_t a0[4], a1[4];
                ldsm_x4(aptrq + s * 32, a0);
                ldsm_x4(aptrq + 16 * 144 + s * 32, a1);
#pragma unroll
                for (int nfp = 0; nfp < 2; nfp++) {
                    uint32_t bb[4];
                    ldsm_x4(bptrq + (uint32_t)(h * 32 + nfp * 16) * 144 + s * 32, bb);
                    mma_f16(acc[0][nfp * 2],     a0, bb);
                    mma_f16(acc[0][nfp * 2 + 1], a0, bb + 2);
                    mma_f16(acc[1][nfp * 2],     a1, bb);
                    mma_f16(acc[1][nfp * 2 + 1], a1, bb + 2);
                }
            }

            // epilogue: masked raw s+1 -> fp16 s_s
#pragma unroll
            for (int mf = 0; mf < 2; mf++) {
                int r0 = m0 + mf * 16 + g;
#pragma unroll
                for (int j = 0; j < 4; j++) {
                    int col = n0q + h * 32 + j * 8 + 2 * c;
                    uint32_t wA = bmt[r0 * 4 + (col >> 5)];
                    uint32_t wB = bmt[(r0 + 8) * 4 + (col >> 5)];
                    int sh = col & 31;
                    float s0 = ((wA >> sh) & 1u)       ? 0.f : acc[mf][j][0] + 1.f;
                    float s1 = ((wA >> (sh + 1)) & 1u) ? 0.f : acc[mf][j][1] + 1.f;
                    float s2 = ((wB >> sh) & 1u)       ? 0.f : acc[mf][j][2] + 1.f;
                    float s3 = ((wB >> (sh + 1)) & 1u) ? 0.f : acc[mf][j][3] + 1.f;
                    *(__half2*)&s_s[r0 * SSP + col]       = __floats2half2_rn(s0, s1);
                    *(__half2*)&s_s[(r0 + 8) * SSP + col] = __floats2half2_rn(s2, s3);
                }
            }
        }
        __syncthreads();   // s_s complete

        // final attn write (normalized fp32) from s_s
#pragma unroll
        for (int i = 0; i < 16; i++) {
            int row = w * 16 + i;
            uint2 raw = *(const uint2*)&s_s[row * SSP + lane * 4];
            float ri = rinv[row];
            __half2 h0 = *(__half2*)&raw.x;
            __half2 h1 = *(__half2*)&raw.y;
            float2 f0 = __half22float2(h0);
            float2 f1 = __half22float2(h1);
            float4 o = make_float4(f0.x * ri, f0.y * ri, f1.x * ri, f1.y * ri);
            __stcs((float4*)(attn + ((size_t)b * LL + q0 + row) * LL +
                             (size_t)kt * 128 + lane * 4), o);
        }

        // PV MMA on raw fp16 scores
#pragma unroll
        for (int s = 0; s < 8; s++) {
            uint32_t a0[4], a1[4];
            ldsm_x4(aptrp + s * 32, a0);
            ldsm_x4(aptrp + 16 * 272 + s * 32, a1);
#pragma unroll
            for (int nfp = 0; nfp < 2; nfp++) {
                uint32_t bb[4];
                ldsm_x4t(vptr + (uint32_t)s * 2304 + (uint32_t)(n0p + nfp * 16) * 2, bb);
                mma_f16(oacc[0][nfp * 2],     a0, bb);
                mma_f16(oacc[0][nfp * 2 + 1], a0, bb + 2);
                mma_f16(oacc[1][nfp * 2],     a1, bb);
                mma_f16(oacc[1][nfp * 2 + 1], a1, bb + 2);
            }
        }
    }

    // O epilogue: scale rows by rinv, write
#pragma unroll
    for (int mf = 0; mf < 2; mf++) {
        int row = m0 + mf * 16 + g;
        float r0 = rinv[row], r1 = rinv[row + 8];
        float* o0 = out + ((size_t)b * LL + q0 + row) * DD;
        float* o1 = o0 + (size_t)8 * DD;
#pragma unroll
        for (int nf = 0; nf < 4; nf++) {
            int col = n0p + nf * 8 + 2 * c;
            *(float2*)(o0 + col) = make_float2(oacc[mf][nf][0] * r0, oacc[mf][nf][1] * r0);
            *(float2*)(o1 + col) = make_float2(oacc[mf][nf][2] * r1, oacc[mf][nf][3] * r1);
        }
    }
}

// ---------------- launch ----------------
extern "C" void kernel_launch(void* const* d_in, const int* in_sizes, int n_in,
                              void* d_out, int out_size) {
    const float* q = (const float*)d_in[0];
    const float* k = (const float*)d_in[1];
    const float* v = (const float*)d_in[2];
    const int* mask = (const int*)d_in[3];

    float* out = (float*)d_out;
    float* attn = out + (size_t)BB * LL * DD;

    cudaFuncSetAttribute(pass1_kernel, cudaFuncAttributeMaxDynamicSharedMemorySize, P1_SMEM);
    cudaFuncSetAttribute(pass2_kernel, cudaFuncAttributeMaxDynamicSharedMemorySize, P2_SMEM);

    norm_kernel<<<(2 * BB * LL) / 16, 256>>>(q, k);
    pass1_kernel<<<dim3(LL / 128, BB), 256, P1_SMEM>>>(mask);
    pass2_kernel<<<dim3(LL / 128, BB), 256, P2_SMEM>>>(v, attn, out);
}

// round 10
// speedup vs baseline: 3.5104x; 1.1035x over previous
#include <cuda_runtime.h>
#include <cuda_fp16.h>
#include <cstdint>

#define BB 32
#define LL 2048
#define DD 64
#define NKT 16            // 2048 / 128

// strides in halfs
#define KSP 72            // q_s / k_s / v_s row stride (144 B)
#define SSP 136           // s_s row stride (272 B)

// pass1 smem (bytes)
#define P1_QS   0
#define P1_KS   18432
#define P1_BMT  36864     // uint32[512]
#define P1_PART 38912     // float[256]
#define P1_SMEM 39936

// pass2 smem (bytes)
#define P2_QS   0
#define P2_KS   18432
#define P2_VS   36864
#define P2_SS   55296     // half[128*136] = 34816
#define P2_RINV 90112     // float[128]
#define P2_SMEM 90624

__device__ __half   g_qh[(size_t)BB * LL * DD];
__device__ __half   g_kh[(size_t)BB * LL * DD];
__device__ __half   g_vh[(size_t)BB * LL * DD];
__device__ uint32_t g_bm[(size_t)BB * LL * (LL / 32)];   // 16.8 MB bitmask
__device__ float    g_rinv[(size_t)BB * LL];

// ---------------- helpers ----------------
__device__ __forceinline__ uint32_t smem_u32(const void* p) {
    uint32_t a;
    asm("{ .reg .u64 t; cvta.to.shared.u64 t, %1; cvt.u32.u64 %0, t; }" : "=r"(a) : "l"(p));
    return a;
}
__device__ __forceinline__ void ldsm_x4(uint32_t addr, uint32_t* r) {
    asm volatile("ldmatrix.sync.aligned.m8n8.x4.shared.b16 {%0,%1,%2,%3}, [%4];"
                 : "=r"(r[0]), "=r"(r[1]), "=r"(r[2]), "=r"(r[3]) : "r"(addr));
}
__device__ __forceinline__ void ldsm_x4t(uint32_t addr, uint32_t* r) {
    asm volatile("ldmatrix.sync.aligned.m8n8.x4.trans.shared.b16 {%0,%1,%2,%3}, [%4];"
                 : "=r"(r[0]), "=r"(r[1]), "=r"(r[2]), "=r"(r[3]) : "r"(addr));
}
__device__ __forceinline__ void mma_f16(float* c, const uint32_t* a, const uint32_t* b) {
    asm volatile(
        "mma.sync.aligned.m16n8k16.row.col.f32.f16.f16.f32 "
        "{%0,%1,%2,%3}, {%4,%5,%6,%7}, {%8,%9}, {%0,%1,%2,%3};"
        : "+f"(c[0]), "+f"(c[1]), "+f"(c[2]), "+f"(c[3])
        : "r"(a[0]), "r"(a[1]), "r"(a[2]), "r"(a[3]), "r"(b[0]), "r"(b[1]));
}
__device__ __forceinline__ void cp16(uint32_t saddr, const void* g) {
    asm volatile("cp.async.cg.shared.global [%0], [%1], 16;" :: "r"(saddr), "l"(g));
}
__device__ __forceinline__ uint32_t h2pack(float a, float b) {
    __half2 h = __floats2half2_rn(a, b);
    return *(uint32_t*)&h;
}

// ---------- Kernel 1: normalize q,k -> fp16; convert v -> fp16 ----------
__global__ __launch_bounds__(256) void norm_kernel(const float* __restrict__ q,
                                                   const float* __restrict__ k,
                                                   const float* __restrict__ v) {
    int t = threadIdx.x;
    int rowInBlk = t >> 4;
    int lane = t & 15;
    long long row = (long long)blockIdx.x * 16 + rowInBlk;
    const long long BL = (long long)BB * LL;

    const float* src;
    __half* dst;
    bool donorm = true;
    long long r2 = row;
    if (r2 < BL) { src = q; dst = g_qh; }
    else if (r2 < 2 * BL) { src = k; dst = g_kh; r2 -= BL; }
    else { src = v; dst = g_vh; r2 -= 2 * BL; donorm = false; }

    const float4 w = *(const float4*)(src + r2 * DD + lane * 4);
    float ss = w.x * w.x + w.y * w.y + w.z * w.z + w.w * w.w;
#pragma unroll
    for (int o = 8; o; o >>= 1) ss += __shfl_xor_sync(0xffffffffu, ss, o, 16);
    float inv = donorm ? (1.0f / fmaxf(sqrtf(ss), 1e-12f)) : 1.0f;
    uint2 u;
    u.x = h2pack(w.x * inv, w.y * inv);
    u.y = h2pack(w.z * inv, w.w * inv);
    *(uint2*)(dst + r2 * DD + lane * 4) = u;
}

// ---------- Pass 1: QK rowsums + mask bitpack ----------
// grid (16, 32), 256 thr. warp w: m0=(w&3)*32 (32q), n0=(w>>2)*64 (64k).
__global__ __launch_bounds__(256, 2) void pass1_kernel(const int* __restrict__ mask) {
    extern __shared__ char smem[];
    __half*   q_s  = (__half*)(smem + P1_QS);
    __half*   k_s  = (__half*)(smem + P1_KS);
    uint32_t* bmt  = (uint32_t*)(smem + P1_BMT);
    float*    part = (float*)(smem + P1_PART);
    const uint32_t smb = smem_u32(smem);

    const int b = blockIdx.y;
    const int q0 = blockIdx.x * 128;
    const int t = threadIdx.x;
    const int w = t >> 5, lane = t & 31;
    const int g = lane >> 2, c = lane & 3;
    const int m0 = (w & 3) * 32, ni = w >> 2, n0 = ni * 64;

    // stage q tile [128][64] fp16
    {
        int r = t >> 1, sg = (t & 1) * 32;
        const __half* qp = g_qh + ((size_t)b * LL + q0 + r) * DD + sg;
#pragma unroll
        for (int i = 0; i < 4; i++)
            *(uint4*)&q_s[r * KSP + sg + i * 8] = *(const uint4*)(qp + i * 8);
    }

    const uint32_t aptr = smb + P1_QS + (uint32_t)(m0 + (lane & 15)) * 144 + (lane >> 4) * 16;
    const uint32_t bptr = smb + P1_KS +
        (uint32_t)(n0 + ((lane >> 4) << 3) + (lane & 7)) * 144 + ((lane >> 3) & 1) * 16;

    const __half* kn = g_kh + (size_t)b * LL * DD;
    float rs[4] = {0.f, 0.f, 0.f, 0.f};

    for (int kt = 0; kt < NKT; kt++) {
        __syncthreads();
        {   // stage k tile [128][64]
            int r = t >> 1, sg = (t & 1) * 32;
            const __half* kp = kn + ((size_t)kt * 128 + r) * DD + sg;
#pragma unroll
            for (int i = 0; i < 4; i++)
                *(uint4*)&k_s[r * KSP + sg + i * 8] = *(const uint4*)(kp + i * 8);
        }
        // ballot bitpack: warp w handles rows w*16..w*16+15
        {
            const int* mbase = mask + ((size_t)b * LL + q0) * LL + (size_t)kt * 128;
#pragma unroll
            for (int i = 0; i < 16; i++) {
                int row = w * 16 + i;
                const int* mr = mbase + (size_t)row * LL;
#pragma unroll
                for (int wq = 0; wq < 4; wq++) {
                    int mv = __ldcs(mr + wq * 32 + lane);
                    uint32_t bits = __ballot_sync(0xffffffffu, mv != 0);
                    if (lane == wq) bmt[row * 4 + wq] = bits;
                }
            }
        }
        __syncthreads();
        // persist bitmask tile (L2-resident for pass 2)
        if (t < 128)
            *(uint4*)&g_bm[((size_t)b * LL + q0 + t) * 64 + kt * 4] = *(const uint4*)&bmt[t * 4];

        // QK MMA
        float acc[2][8][4];
#pragma unroll
        for (int mf = 0; mf < 2; mf++)
#pragma unroll
            for (int nf = 0; nf < 8; nf++)
#pragma unroll
                for (int e = 0; e < 4; e++) acc[mf][nf][e] = 0.f;

#pragma unroll
        for (int s = 0; s < 4; s++) {
            uint32_t a0[4], a1[4];
            ldsm_x4(aptr + s * 32, a0);
            ldsm_x4(aptr + 16 * 144 + s * 32, a1);
#pragma unroll
            for (int nfp = 0; nfp < 4; nfp++) {
                uint32_t bb[4];
                ldsm_x4(bptr + (uint32_t)nfp * 16 * 144 + s * 32, bb);
                mma_f16(acc[0][nfp * 2],     a0, bb);
                mma_f16(acc[0][nfp * 2 + 1], a0, bb + 2);
                mma_f16(acc[1][nfp * 2],     a1, bb);
                mma_f16(acc[1][nfp * 2 + 1], a1, bb + 2);
            }
        }

        // rowsum epilogue (bits from smem)
#pragma unroll
        for (int mf = 0; mf < 2; mf++) {
            int r0 = m0 + mf * 16 + g;
#pragma unroll
            for (int nf = 0; nf < 8; nf++) {
                int col = n0 + nf * 8 + 2 * c;
                uint32_t wA = bmt[r0 * 4 + (col >> 5)];
                uint32_t wB = bmt[(r0 + 8) * 4 + (col >> 5)];
                int sh = col & 31;
                float s0 = ((wA >> sh) & 1u)       ? 0.f : acc[mf][nf][0] + 1.f;
                float s1 = ((wA >> (sh + 1)) & 1u) ? 0.f : acc[mf][nf][1] + 1.f;
                float s2 = ((wB >> sh) & 1u)       ? 0.f : acc[mf][nf][2] + 1.f;
                float s3 = ((wB >> (sh + 1)) & 1u) ? 0.f : acc[mf][nf][3] + 1.f;
                rs[mf * 2 + 0] += s0 + s1;
                rs[mf * 2 + 1] += s2 + s3;
            }
        }
    }

    // rowsums: reduce over c lanes, combine two ni halves via smem
#pragma unroll
    for (int i = 0; i < 4; i++) {
        float vs = rs[i];
        vs += __shfl_xor_sync(0xffffffffu, vs, 1);
        vs += __shfl_xor_sync(0xffffffffu, vs, 2);
        rs[i] = vs;
    }
    if (c == 0) {
        part[(m0 + g) * 2 + ni]      = rs[0];
        part[(m0 + g + 8) * 2 + ni]  = rs[1];
        part[(m0 + 16 + g) * 2 + ni] = rs[2];
        part[(m0 + 24 + g) * 2 + ni] = rs[3];
    }
    __syncthreads();
    if (t < 128)
        g_rinv[(size_t)b * LL + q0 + t] =
            1.0f / fmaxf(part[t * 2] + part[t * 2 + 1], 1e-12f);
}

// ---------- Pass 2: QK recompute -> attn write + PV (reg-resident A) ----------
// grid (16, 32), 256 thr. warp w owns q rows w*16..w*16+15, full 128 k per tile.
__global__ __launch_bounds__(256, 2) void pass2_kernel(float* __restrict__ attn,
                                                       float* __restrict__ out) {
    extern __shared__ char smem[];
    __half* q_s  = (__half*)(smem + P2_QS);
    __half* s_s  = (__half*)(smem + P2_SS);
    float*  rinv = (float*)(smem + P2_RINV);
    const uint32_t smb = smem_u32(smem);

    const int b = blockIdx.y;
    const int q0 = blockIdx.x * 128;
    const int t = threadIdx.x;
    const int w = t >> 5, lane = t & 31;
    const int g = lane >> 2, c = lane & 3;
    const int r0 = w * 16;

    if (t < 128) rinv[t] = g_rinv[(size_t)b * LL + q0 + t];

    // stage q tile
    {
        int r = t >> 1, sg = (t & 1) * 32;
        const __half* qp = g_qh + ((size_t)b * LL + q0 + r) * DD + sg;
#pragma unroll
        for (int i = 0; i < 4; i++)
            *(uint4*)&q_s[r * KSP + sg + i * 8] = *(const uint4*)(qp + i * 8);
    }

    const uint32_t aptr = smb + P2_QS + (uint32_t)(r0 + (lane & 15)) * 144 + (lane >> 4) * 16;
    const uint32_t bptr = smb + P2_KS +
        (uint32_t)(((lane >> 4) << 3) + (lane & 7)) * 144 + ((lane >> 3) & 1) * 16;
    const uint32_t vptr = smb + P2_VS + (uint32_t)(lane & 15) * 144 + (lane >> 4) * 16;

    float oacc[8][4];
#pragma unroll
    for (int nb = 0; nb < 8; nb++)
#pragma unroll
        for (int e = 0; e < 4; e++) oacc[nb][e] = 0.f;

    const __half* kn = g_kh + (size_t)b * LL * DD;
    const __half* vn = g_vh + (size_t)b * LL * DD;
    const uint32_t* bmrA = g_bm + ((size_t)b * LL + q0 + r0 + g) * 64;
    const uint32_t* bmrB = bmrA + (size_t)8 * 64;

    for (int kt = 0; kt < NKT; kt++) {
        __syncthreads();   // all warps done with k_s/v_s of prev tile
        // cp.async stage k,v tiles [128][64] fp16
        {
            const __half* kbase = kn + (size_t)kt * 128 * DD;
            const __half* vbase = vn + (size_t)kt * 128 * DD;
#pragma unroll
            for (int i = 0; i < 4; i++) {
                int idx = t + i * 256;
                int r = idx >> 3, seg = idx & 7;
                cp16(smb + P2_KS + r * 144 + seg * 16, kbase + r * 64 + seg * 8);
                cp16(smb + P2_VS + r * 144 + seg * 16, vbase + r * 64 + seg * 8);
            }
        }
        asm volatile("cp.async.commit_group;");
        // bitmask for this thread's two rows (L2-hot)
        uint4 bA = *(const uint4*)(bmrA + kt * 4);
        uint4 bB = *(const uint4*)(bmrB + kt * 4);
        uint32_t bmA[4] = {bA.x, bA.y, bA.z, bA.w};
        uint32_t bmB[4] = {bB.x, bB.y, bB.z, bB.w};
        asm volatile("cp.async.wait_group 0;");
        __syncthreads();

        // two 64-col halves: QK -> epilogue -> PV (A from registers)
#pragma unroll
        for (int h = 0; h < 2; h++) {
            float acc[8][4];
#pragma unroll
            for (int nf = 0; nf < 8; nf++)
#pragma unroll
                for (int e = 0; e < 4; e++) acc[nf][e] = 0.f;

#pragma unroll
            for (int s = 0; s < 4; s++) {
                uint32_t a[4];
                ldsm_x4(aptr + s * 32, a);
#pragma unroll
                for (int nb = 0; nb < 4; nb++) {
                    uint32_t bb[4];
                    ldsm_x4(bptr + (uint32_t)(h * 4 + nb) * 2304 + s * 32, bb);
                    mma_f16(acc[nb * 2],     a, bb);
                    mma_f16(acc[nb * 2 + 1], a, bb + 2);
                }
            }

#pragma unroll
            for (int ks = 0; ks < 4; ks++) {
                uint32_t af[4];
#pragma unroll
                for (int p = 0; p < 2; p++) {
                    int nf = 2 * ks + p;
                    int col = h * 64 + nf * 8 + 2 * c;
                    uint32_t wA = bmA[col >> 5];
                    uint32_t wB = bmB[col >> 5];
                    int sh = col & 31;
                    float s0 = ((wA >> sh) & 1u)       ? 0.f : acc[nf][0] + 1.f;
                    float s1 = ((wA >> (sh + 1)) & 1u) ? 0.f : acc[nf][1] + 1.f;
                    float s2 = ((wB >> sh) & 1u)       ? 0.f : acc[nf][2] + 1.f;
                    float s3 = ((wB >> (sh + 1)) & 1u) ? 0.f : acc[nf][3] + 1.f;
                    uint32_t hA = h2pack(s0, s1);
                    uint32_t hB = h2pack(s2, s3);
                    af[p * 2]     = hA;
                    af[p * 2 + 1] = hB;
                    *(uint32_t*)&s_s[(r0 + g) * SSP + col]     = hA;
                    *(uint32_t*)&s_s[(r0 + g + 8) * SSP + col] = hB;
                }
                int gks = h * 4 + ks;
#pragma unroll
                for (int db = 0; db < 4; db++) {
                    uint32_t bb[4];
                    ldsm_x4t(vptr + (uint32_t)gks * 2304 + db * 32, bb);
                    mma_f16(oacc[db * 2],     af, bb);
                    mma_f16(oacc[db * 2 + 1], af, bb + 2);
                }
            }
        }

        __syncwarp();   // s_s rows complete within warp
        // attn write (normalized fp32), warp-private rows, coalesced
#pragma unroll
        for (int i = 0; i < 16; i++) {
            int row = r0 + i;
            uint2 raw = *(const uint2*)&s_s[row * SSP + lane * 4];
            float ri = rinv[row];
            float2 f0 = __half22float2(*(__half2*)&raw.x);
            float2 f1 = __half22float2(*(__half2*)&raw.y);
            float4 o = make_float4(f0.x * ri, f0.y * ri, f1.x * ri, f1.y * ri);
            __stcs((float4*)(attn + ((size_t)b * LL + q0 + row) * LL +
                             (size_t)kt * 128 + lane * 4), o);
        }
        __syncwarp();
    }

    // O epilogue: scale rows by rinv, write
    float riA = rinv[r0 + g], riB = rinv[r0 + g + 8];
    float* o0 = out + ((size_t)b * LL + q0 + r0 + g) * DD;
    float* o1 = o0 + (size_t)8 * DD;
#pragma unroll
    for (int nb = 0; nb < 8; nb++) {
        int col = nb * 8 + 2 * c;
        *(float2*)(o0 + col) = make_float2(oacc[nb][0] * riA, oacc[nb][1] * riA);
        *(float2*)(o1 + col) = make_float2(oacc[nb][2] * riB, oacc[nb][3] * riB);
    }
}

// ---------------- launch ----------------
extern "C" void kernel_launch(void* const* d_in, const int* in_sizes, int n_in,
                              void* d_out, int out_size) {
    const float* q = (const float*)d_in[0];
    const float* k = (const float*)d_in[1];
    const float* v = (const float*)d_in[2];
    const int* mask = (const int*)d_in[3];

    float* out = (float*)d_out;
    float* attn = out + (size_t)BB * LL * DD;

    cudaFuncSetAttribute(pass1_kernel, cudaFuncAttributeMaxDynamicSharedMemorySize, P1_SMEM);
    cudaFuncSetAttribute(pass2_kernel, cudaFuncAttributeMaxDynamicSharedMemorySize, P2_SMEM);

    norm_kernel<<<(3 * BB * LL) / 16, 256>>>(q, k, v);
    pass1_kernel<<<dim3(LL / 128, BB), 256, P1_SMEM>>>(mask);
    pass2_kernel<<<dim3(LL / 128, BB), 256, P2_SMEM>>>(attn, out);
}